// round 4
// baseline (speedup 1.0000x reference)
#include <cuda_runtime.h>

// Problem constants (fixed shapes: x = (2, 64, 256, 256) fp32, stoken_size = 16)
#define BB   2
#define CC   64
#define HH   256
#define WW   256
#define SS   16
#define NH   16
#define NW   16
#define NSP  256      // nH*nW
#define NPIX 65536    // H*W

// Scratch (device globals; no allocations allowed)
__device__ float g_cent0[BB*NSP*CC];
__device__ float g_cent1[BB*NSP*CC];
// per-block partials: [b][blk][k(9)][c(64)]
__device__ float g_part [BB*NSP*9*64];
// per-quarter weight sums from iter0: [b][blk][q(4)][k(9)]
__device__ float g_den0 [BB*NSP*4*9];
// iter0 weights: [b][blk][k(9)][pix(256)]
__device__ __align__(16) float g_w0 [BB*NSP*9*256];
// final weights: [b][blk][k(9)][pix(256)]
__device__ __align__(16) float g_w  [BB*NSP*9*256];

// ---------------------------------------------------------------------------
// K1: initial centroids = per-16x16-block channel means.
// CTA = (b, c, block-row by). 2048 CTAs, 256 threads, fully coalesced LDG.128.
// ---------------------------------------------------------------------------
__global__ __launch_bounds__(256) void k_means(const float* __restrict__ x)
{
    int bid = blockIdx.x;
    int by  = bid & 15;
    int bc  = bid >> 4;          // b*64 + c
    int b   = bc >> 6, c = bc & 63;

    const float4* xp = (const float4*)(x + (size_t)bc*NPIX + (size_t)by*16*WW);
    int tid = threadIdx.x;
    int fc  = tid & 63;          // float4 column 0..63
    int g   = tid >> 6;          // row group 0..3

    float4 s = make_float4(0.f, 0.f, 0.f, 0.f);
    #pragma unroll
    for (int r = 0; r < 4; r++) {
        float4 v = xp[(g*4 + r)*64 + fc];
        s.x += v.x; s.y += v.y; s.z += v.z; s.w += v.w;
    }

    __shared__ float4 sm4[4][64];
    __shared__ float  smc[64];
    sm4[g][fc] = s;
    __syncthreads();

    if (tid < 64) {
        float4 a = sm4[0][tid], b4 = sm4[1][tid], c4 = sm4[2][tid], d4 = sm4[3][tid];
        smc[tid] = (a.x+a.y+a.z+a.w) + (b4.x+b4.y+b4.z+b4.w)
                 + (c4.x+c4.y+c4.z+c4.w) + (d4.x+d4.y+d4.z+d4.w);
    }
    __syncthreads();

    if (tid < 16) {
        float m = (smc[4*tid] + smc[4*tid+1] + smc[4*tid+2] + smc[4*tid+3]) * (1.f/256.f);
        g_cent0[((size_t)(b*NSP + by*16 + tid))*CC + c] = m;
    }
}

// ---------------------------------------------------------------------------
// K2/K4: dot products + softmax weights, quarter-block CTAs for latency hiding.
// grid = BB*NSP*4 = 2048 CTAs, 256 threads.
// Thread (pl, sub): pixel pl (of 64 in this quarter), channels sub*16..+16.
// 16 independent LDGs per thread (MLP 16); 18-shfl reduce across the 4 subs.
// iter==0: centroids = g_cent0, weights -> g_w0, per-quarter den -> g_den0.
// iter==1: centroids = g_cent1, weights -> g_w.
// ---------------------------------------------------------------------------
__global__ __launch_bounds__(256) void k_dots(const float* __restrict__ x, int iter)
{
    const float* __restrict__ cent = iter ? g_cent1 : g_cent0;
    float* __restrict__ wout       = iter ? g_w     : g_w0;

    __shared__ __align__(16) float cent_s[9*64];
    __shared__ float csq_s[9];
    __shared__ float dsm[8][9];

    int bid = blockIdx.x;
    int b   = bid >> 10;
    int rem = bid & 1023;
    int blk = rem >> 2;
    int q   = rem & 3;
    int sy  = blk >> 4, sx = blk & 15;
    int tid = threadIdx.x;

    // stage 9 candidate centroids
    for (int i = tid; i < 9*64; i += 256) {
        int k = i >> 6, c = i & 63;
        int cy = sy + (k/3) - 1, cx = sx + (k%3) - 1;
        float v = 0.f;
        if (cy >= 0 && cy < NH && cx >= 0 && cx < NW)
            v = cent[((size_t)(b*NSP + cy*NW + cx))*CC + c];
        cent_s[i] = v;
    }
    __syncthreads();
    if (tid < 9) {
        float s = 0.f;
        #pragma unroll 8
        for (int c = 0; c < 64; c++) { float v = cent_s[tid*64 + c]; s = fmaf(v, v, s); }
        csq_s[tid] = s;
    }
    __syncthreads();

    int pl  = tid >> 2;            // pixel-in-quarter 0..63
    int sub = tid & 3;             // channel slice 0..3
    int row = q*4 + (pl >> 4);     // row in block 0..15
    int col = pl & 15;
    int n   = (sy*SS + row)*WW + sx*SS + col;
    const float* xp = x + (size_t)b*CC*NPIX + (size_t)(sub*16)*NPIX + n;

    float p[16];
    #pragma unroll
    for (int i = 0; i < 16; i++) p[i] = xp[(size_t)i*NPIX];

    float dot[9];
    #pragma unroll
    for (int k = 0; k < 9; k++) dot[k] = 0.f;
    #pragma unroll
    for (int i = 0; i < 16; i++) {
        #pragma unroll
        for (int k = 0; k < 9; k++)
            dot[k] = fmaf(p[i], cent_s[k*64 + sub*16 + i], dot[k]);
    }
    // reduce across the 4 sub-lanes (exact: power-of-two pair sums)
    #pragma unroll
    for (int k = 0; k < 9; k++) {
        dot[k] += __shfl_xor_sync(0xffffffffu, dot[k], 1);
        dot[k] += __shfl_xor_sync(0xffffffffu, dot[k], 2);
    }

    float l[9];
    float m = -1e30f;
    #pragma unroll
    for (int k = 0; k < 9; k++) {
        int cy = sy + (k/3) - 1, cx = sx + (k%3) - 1;
        bool valid = (cy >= 0 && cy < NH && cx >= 0 && cx < NW);
        l[k] = valid ? (2.f*dot[k] - csq_s[k]) : -1e30f;
        m = fmaxf(m, l[k]);
    }
    float e[9], ssum = 0.f;
    #pragma unroll
    for (int k = 0; k < 9; k++) {
        e[k] = (l[k] > -1e29f) ? __expf(l[k] - m) : 0.f;
        ssum += e[k];
    }
    float inv = 1.f / ssum;
    #pragma unroll
    for (int k = 0; k < 9; k++) e[k] *= inv;

    // store weights: k<8 handled by sub==(k&3), k==8 by sub==0 (no dyn indexing)
    float* wp = wout + ((size_t)(b*NSP + blk)*9)*256 + q*64 + pl;
    #pragma unroll
    for (int k = 0; k < 9; k++) {
        bool mine = (k < 8) ? (sub == (k & 3)) : (sub == 0);
        if (mine) wp[(size_t)k*256] = e[k];
    }

    // iter0: per-quarter den[k] = sum over 64 pixels of w[k]
    if (!iter) {
        int wid = tid >> 5, lane = tid & 31;
        float dk[9];
        #pragma unroll
        for (int k = 0; k < 9; k++) {
            float v = e[k];
            #pragma unroll
            for (int o = 16; o > 0; o >>= 1) v += __shfl_xor_sync(0xffffffffu, v, o);
            dk[k] = v;           // = 4 * (sum over this warp's 8 pixels)
        }
        if (lane == 0) {
            #pragma unroll
            for (int k = 0; k < 9; k++) dsm[wid][k] = dk[k];
        }
        __syncthreads();
        if (tid < 9) {
            float s = 0.f;
            #pragma unroll
            for (int w = 0; w < 8; w++) s += dsm[w][tid];
            g_den0[((size_t)((b*NSP + blk)*4 + q))*9 + tid] = s * 0.25f;
        }
    }
}

// ---------------------------------------------------------------------------
// K3: per-block partials partial[k][c] = sum_pix w0[k][pix] * x[c][pix].
// grid = 512, 256 threads. Weights staged in smem; x re-read (L2-hot).
// Warp w handles channels [w*8, w*8+8) in 2 groups of 4; butterfly reduce.
// ---------------------------------------------------------------------------
__global__ __launch_bounds__(256) void k_part(const float* __restrict__ x)
{
    __shared__ float Wsh[9*256];

    int bid = blockIdx.x;
    int b   = bid >> 8;
    int blk = bid & 255;
    int sy  = blk >> 4, sx = blk & 15;
    int tid = threadIdx.x;

    const float* wsrc = g_w0 + ((size_t)(b*NSP + blk)*9)*256;
    #pragma unroll
    for (int i = 0; i < 9; i++) Wsh[i*256 + tid] = wsrc[i*256 + tid];
    __syncthreads();

    int wid = tid >> 5, lane = tid & 31;
    const float* xt = x + (size_t)b*CC*NPIX + (size_t)(sy*SS)*WW + sx*SS;
    float* pdst = g_part + ((size_t)(b*NSP + blk)*9)*64;

    #pragma unroll
    for (int grp = 0; grp < 2; grp++) {
        int cbase = wid*8 + grp*4;
        float acc[4][9];
        #pragma unroll
        for (int cc = 0; cc < 4; cc++)
            #pragma unroll
            for (int k = 0; k < 9; k++) acc[cc][k] = 0.f;

        #pragma unroll
        for (int j = 0; j < 8; j++) {
            int pix = j*32 + lane;
            int row = pix >> 4, col = pix & 15;
            float w[9];
            #pragma unroll
            for (int k = 0; k < 9; k++) w[k] = Wsh[k*256 + pix];
            #pragma unroll
            for (int cc = 0; cc < 4; cc++) {
                float p = xt[(size_t)(cbase + cc)*NPIX + row*WW + col];
                #pragma unroll
                for (int k = 0; k < 9; k++) acc[cc][k] = fmaf(w[k], p, acc[cc][k]);
            }
        }
        #pragma unroll
        for (int cc = 0; cc < 4; cc++)
            #pragma unroll
            for (int k = 0; k < 9; k++)
                #pragma unroll
                for (int o = 16; o > 0; o >>= 1)
                    acc[cc][k] += __shfl_xor_sync(0xffffffffu, acc[cc][k], o);
        #pragma unroll
        for (int k = 0; k < 9; k++) {
            if (lane == k) {
                #pragma unroll
                for (int cc = 0; cc < 4; cc++)
                    pdst[(size_t)k*64 + cbase + cc] = acc[cc][k];
            }
        }
    }
}

// ---------------------------------------------------------------------------
// K3b: gather per-superpixel centroid update (no atomics).
// grid = 512 (b,s), block = 64 (one thread per channel).
// ---------------------------------------------------------------------------
__global__ __launch_bounds__(64) void k_update()
{
    int bid = blockIdx.x;
    int b   = bid >> 8;
    int s   = bid & 255;
    int sy  = s >> 4, sx = s & 15;
    int c   = threadIdx.x;

    __shared__ float dsm[9];
    if (c < 9) {
        int dy = c/3 - 1, dx = c%3 - 1;
        int ny = sy + dy, nx = sx + dx;
        float d = 0.f;
        if (ny >= 0 && ny < NH && nx >= 0 && nx < NW) {
            const float* dp = g_den0 + ((size_t)((b*NSP + ny*NW + nx)*4))*9 + (8 - c);
            #pragma unroll
            for (int q = 0; q < 4; q++) d += dp[q*9];
        }
        dsm[c] = d;
    }
    __syncthreads();

    float den = 0.f;
    #pragma unroll
    for (int j = 0; j < 9; j++) den += dsm[j];

    float num = 0.f;
    #pragma unroll
    for (int j = 0; j < 9; j++) {
        int dy = j/3 - 1, dx = j%3 - 1;
        int ny = sy + dy, nx = sx + dx;
        if (ny >= 0 && ny < NH && nx >= 0 && nx < NW) {
            num += g_part[((size_t)((b*NSP + ny*NW + nx)*9 + (8 - j)))*64 + c];
        }
    }
    g_cent1[((size_t)(b*NSP + s))*CC + c] = num / (den + 1e-16f);
}

// ---------------------------------------------------------------------------
// K5: streaming output writer (writes all 134 MB exactly once, STG.128).
// grid = BB*NSP*4 = 2048 CTAs, block = 256.
// ---------------------------------------------------------------------------
__global__ __launch_bounds__(256) void k_write(float* __restrict__ out)
{
    int bid = blockIdx.x;
    int b   = bid >> 10;
    int rem = bid & 1023;
    int s   = rem >> 2;
    int q   = rem & 3;
    int sy  = s >> 4, sx = s & 15;
    int y0  = q * 64;

    float4* op = (float4*)(out + ((size_t)(b*NSP + s) << 16)) + (y0 << 6);
    const float4* wbase = (const float4*)g_w;

    int tid = threadIdx.x;
    #pragma unroll
    for (int it = 0; it < 16; it++) {
        int idx = it*256 + tid;
        int y   = y0 + (idx >> 6);
        int x4  = idx & 63;
        int by  = y >> 4;
        int bx  = x4 >> 2;
        int dy  = sy - by;
        int dx  = sx - bx;
        float4 v = make_float4(0.f, 0.f, 0.f, 0.f);
        if (dy >= -1 && dy <= 1 && dx >= -1 && dx <= 1) {
            int k   = (dy + 1)*3 + (dx + 1);
            int blk = by*NW + bx;
            int py  = y & 15;
            int px4 = x4 & 3;
            v = wbase[(((size_t)(b*NSP + blk)*9 + k) << 6) + (py << 2) + px4];
        }
        op[idx] = v;
    }
}

// ---------------------------------------------------------------------------
extern "C" void kernel_launch(void* const* d_in, const int* in_sizes, int n_in,
                              void* d_out, int out_size)
{
    const float* x = (const float*)d_in[0];
    float* out = (float*)d_out;

    k_means<<<BB*CC*16, 256>>>(x);
    k_dots <<<BB*NSP*4, 256>>>(x, 0);
    k_part <<<BB*NSP,   256>>>(x);
    k_update<<<BB*NSP,   64>>>();
    k_dots <<<BB*NSP*4, 256>>>(x, 1);
    k_write<<<BB*NSP*4, 256>>>(out);
}

// round 5
// speedup vs baseline: 1.2767x; 1.2767x over previous
#include <cuda_runtime.h>

// Problem constants (fixed shapes: x = (2, 64, 256, 256) fp32, stoken_size = 16)
#define BB   2
#define CC   64
#define HH   256
#define WW   256
#define SS   16
#define NH   16
#define NW   16
#define NSP  256      // nH*nW
#define NPIX 65536    // H*W

// cent2 layout: [k][half][CH_STR] with CH_STR=36 -> half-lanes' LDS banks differ
// by 4 (36 mod 32), so the 2-way broadcast read is bank-conflict-free.
#define CH_STR 36

// Scratch (device globals; no allocations allowed)
__device__ float g_cent0[BB*NSP*CC];
__device__ float g_cent1[BB*NSP*CC];
// per-(block,half) partials: [b][blk][half][k(9)][c(64)]
__device__ float g_part [BB*NSP*2*9*64];
// per-(block,half) weight sums: [b][blk][half][k(9)]
__device__ float g_den0 [BB*NSP*2*9];
// final weights: [b][blk][k(9)][pix(256)]
__device__ __align__(16) float g_w  [BB*NSP*9*256];

// ---------------------------------------------------------------------------
// K1: initial centroids = per-16x16-block channel means.
// CTA = (b, c, block-row by). 2048 CTAs, 256 threads, fully coalesced LDG.128.
// ---------------------------------------------------------------------------
__global__ __launch_bounds__(256) void k_means(const float* __restrict__ x)
{
    int bid = blockIdx.x;
    int by  = bid & 15;
    int bc  = bid >> 4;          // b*64 + c
    int b   = bc >> 6, c = bc & 63;

    const float4* xp = (const float4*)(x + (size_t)bc*NPIX + (size_t)by*16*WW);
    int tid = threadIdx.x;
    int fc  = tid & 63;          // float4 column 0..63
    int g   = tid >> 6;          // row group 0..3

    float4 s = make_float4(0.f, 0.f, 0.f, 0.f);
    #pragma unroll
    for (int r = 0; r < 4; r++) {
        float4 v = xp[(g*4 + r)*64 + fc];
        s.x += v.x; s.y += v.y; s.z += v.z; s.w += v.w;
    }

    __shared__ float4 sm4[4][64];
    __shared__ float  smc[64];
    sm4[g][fc] = s;
    __syncthreads();

    if (tid < 64) {
        float4 a = sm4[0][tid], b4 = sm4[1][tid], c4 = sm4[2][tid], d4 = sm4[3][tid];
        smc[tid] = (a.x+a.y+a.z+a.w) + (b4.x+b4.y+b4.z+b4.w)
                 + (c4.x+c4.y+c4.z+c4.w) + (d4.x+d4.y+d4.z+d4.w);
    }
    __syncthreads();

    if (tid < 16) {
        float m = (smc[4*tid] + smc[4*tid+1] + smc[4*tid+2] + smc[4*tid+3]) * (1.f/256.f);
        g_cent0[((size_t)(b*NSP + by*16 + tid))*CC + c] = m;
    }
}

// ---------------------------------------------------------------------------
// Shared helper: stage 9 candidate centroids into cent2[k][h][CH_STR] + csq.
// ---------------------------------------------------------------------------
__device__ __forceinline__ void stage_cent(const float* __restrict__ cent,
                                           float* cent2, float* csq_s,
                                           int b, int sy, int sx, int tid)
{
    for (int i = tid; i < 9*64; i += 256) {
        int k = i >> 6, c = i & 63;
        int cy = sy + (k/3) - 1, cx = sx + (k%3) - 1;
        float v = 0.f;
        if (cy >= 0 && cy < NH && cx >= 0 && cx < NW)
            v = cent[((size_t)(b*NSP + cy*NW + cx))*CC + c];
        cent2[k*(2*CH_STR) + (c >> 5)*CH_STR + (c & 31)] = v;
    }
    __syncthreads();
    if (tid < 18) {
        int k = tid >> 1, h = tid & 1;
        float s = 0.f;
        #pragma unroll 8
        for (int c = 0; c < 32; c++) {
            float v = cent2[k*(2*CH_STR) + h*CH_STR + c];
            s = fmaf(v, v, s);
        }
        // accumulate both halves into csq_s[k] without a race: h==0 writes, then h==1 adds
        if (h == 0) csq_s[k] = s;
        __syncwarp(0x0003ffffu >> 0);   // first 18 threads are in warp 0? no: 18 <= 32, yes warp 0
        if (h == 1) csq_s[k] += s;
    }
    __syncthreads();
}

// ---------------------------------------------------------------------------
// K2: iteration 0 over HALF-blocks. CTA=(b,blk,half): 1024 CTAs, 256 threads.
// Thread = (pl 0..127 pixel-in-half, h 0..1 channel half). 32 LDGs/thread.
// Phase B: dots (shfl-merge halves) + softmax -> Wsh[128][9].
// Phase C: half-partials partial[k][c] over this CTA's 128 pixels (L1-hot
// re-read), plus per-half den[k].
// ---------------------------------------------------------------------------
__global__ __launch_bounds__(256) void k_iter0(const float* __restrict__ x)
{
    __shared__ float cent2[9*2*CH_STR];
    __shared__ float csq_s[9];
    __shared__ float Wsh[128*9];
    __shared__ float dsm[8][9];

    int bid  = blockIdx.x;
    int b    = bid >> 9;
    int rem  = bid & 511;
    int blk  = rem >> 1;
    int half = rem & 1;
    int sy   = blk >> 4, sx = blk & 15;
    int tid  = threadIdx.x;

    stage_cent(g_cent0, cent2, csq_s, b, sy, sx, tid);

    // phase B
    int pl  = tid >> 1;                 // 0..127
    int h   = tid & 1;                  // channel half
    int row = half*8 + (pl >> 4);
    int col = pl & 15;
    const float* xp = x + (size_t)b*CC*NPIX + (size_t)(h*32)*NPIX
                        + (size_t)(sy*SS + row)*WW + sx*SS + col;

    float p[32];
    #pragma unroll
    for (int i = 0; i < 32; i++) p[i] = xp[(size_t)i*NPIX];

    float dot[9];
    #pragma unroll
    for (int k = 0; k < 9; k++) dot[k] = 0.f;
    #pragma unroll
    for (int i = 0; i < 32; i++) {
        #pragma unroll
        for (int k = 0; k < 9; k++)
            dot[k] = fmaf(p[i], cent2[k*(2*CH_STR) + h*CH_STR + i], dot[k]);
    }
    #pragma unroll
    for (int k = 0; k < 9; k++)
        dot[k] += __shfl_xor_sync(0xffffffffu, dot[k], 1);

    float l[9];
    float m = -1e30f;
    #pragma unroll
    for (int k = 0; k < 9; k++) {
        int cy = sy + (k/3) - 1, cx = sx + (k%3) - 1;
        bool valid = (cy >= 0 && cy < NH && cx >= 0 && cx < NW);
        l[k] = valid ? (2.f*dot[k] - csq_s[k]) : -1e30f;
        m = fmaxf(m, l[k]);
    }
    float e[9], ssum = 0.f;
    #pragma unroll
    for (int k = 0; k < 9; k++) {
        e[k] = (l[k] > -1e29f) ? __expf(l[k] - m) : 0.f;
        ssum += e[k];
    }
    float inv = 1.f / ssum;
    #pragma unroll
    for (int k = 0; k < 9; k++) e[k] *= inv;

    if (h == 0) {
        #pragma unroll
        for (int k = 0; k < 9; k++) Wsh[pl*9 + k] = e[k];
    }

    // per-half den[k]: each pixel counted twice across the 2 h-lanes -> *0.5
    {
        int wid = tid >> 5, lane = tid & 31;
        #pragma unroll
        for (int k = 0; k < 9; k++) {
            float v = e[k];
            #pragma unroll
            for (int o = 16; o > 0; o >>= 1) v += __shfl_xor_sync(0xffffffffu, v, o);
            if (lane == 0) dsm[wid][k] = v;
        }
        __syncthreads();
        if (tid < 9) {
            float s = 0.f;
            #pragma unroll
            for (int w = 0; w < 8; w++) s += dsm[w][tid];
            g_den0[((size_t)((b*NSP + blk)*2 + half))*9 + tid] = s * 0.5f;
        }
    }

    // phase C: warp wid -> channels [wid*8, wid*8+8) in 2 groups of 4.
    int wid = tid >> 5, lane = tid & 31;
    const float* xt = x + (size_t)b*CC*NPIX + (size_t)(sy*SS + half*8)*WW + sx*SS;
    float* pdst = g_part + ((size_t)((b*NSP + blk)*2 + half)*9)*64;

    #pragma unroll
    for (int grp = 0; grp < 2; grp++) {
        int cbase = wid*8 + grp*4;
        float acc[4][9];
        #pragma unroll
        for (int cc = 0; cc < 4; cc++)
            #pragma unroll
            for (int k = 0; k < 9; k++) acc[cc][k] = 0.f;

        #pragma unroll
        for (int j = 0; j < 4; j++) {
            int pix = j*32 + lane;                // 0..127 within half
            int prow = pix >> 4, pcol = pix & 15;
            float w[9];
            #pragma unroll
            for (int k = 0; k < 9; k++) w[k] = Wsh[pix*9 + k];
            #pragma unroll
            for (int cc = 0; cc < 4; cc++) {
                float pv = xt[(size_t)(cbase + cc)*NPIX + prow*WW + pcol];
                #pragma unroll
                for (int k = 0; k < 9; k++) acc[cc][k] = fmaf(w[k], pv, acc[cc][k]);
            }
        }
        #pragma unroll
        for (int cc = 0; cc < 4; cc++)
            #pragma unroll
            for (int k = 0; k < 9; k++)
                #pragma unroll
                for (int o = 16; o > 0; o >>= 1)
                    acc[cc][k] += __shfl_xor_sync(0xffffffffu, acc[cc][k], o);
        #pragma unroll
        for (int k = 0; k < 9; k++) {
            if (lane == k) {
                #pragma unroll
                for (int cc = 0; cc < 4; cc++)
                    pdst[(size_t)k*64 + cbase + cc] = acc[cc][k];
            }
        }
    }
}

// ---------------------------------------------------------------------------
// K3: gather per-superpixel centroid update (no atomics).
// grid = 512 (b,s), block = 64 (one thread per channel).
// ---------------------------------------------------------------------------
__global__ __launch_bounds__(64) void k_update()
{
    int bid = blockIdx.x;
    int b   = bid >> 8;
    int s   = bid & 255;
    int sy  = s >> 4, sx = s & 15;
    int c   = threadIdx.x;

    __shared__ float dsm[9];
    if (c < 9) {
        int dy = c/3 - 1, dx = c%3 - 1;
        int ny = sy + dy, nx = sx + dx;
        float d = 0.f;
        if (ny >= 0 && ny < NH && nx >= 0 && nx < NW) {
            int nb = ny*NW + nx;
            d = g_den0[((size_t)((b*NSP + nb)*2 + 0))*9 + (8 - c)]
              + g_den0[((size_t)((b*NSP + nb)*2 + 1))*9 + (8 - c)];
        }
        dsm[c] = d;
    }
    __syncthreads();

    float den = 0.f;
    #pragma unroll
    for (int j = 0; j < 9; j++) den += dsm[j];

    float num = 0.f;
    #pragma unroll
    for (int j = 0; j < 9; j++) {
        int dy = j/3 - 1, dx = j%3 - 1;
        int ny = sy + dy, nx = sx + dx;
        if (ny >= 0 && ny < NH && nx >= 0 && nx < NW) {
            int nb = ny*NW + nx;
            num += g_part[((size_t)((b*NSP + nb)*2 + 0)*9 + (8 - j))*64 + c]
                 + g_part[((size_t)((b*NSP + nb)*2 + 1)*9 + (8 - j))*64 + c];
        }
    }
    g_cent1[((size_t)(b*NSP + s))*CC + c] = num / (den + 1e-16f);
}

// ---------------------------------------------------------------------------
// K4: iteration 1 weights over HALF-blocks -> g_w[b][blk][k][pix].
// Same split as k_iter0 phase B; 1024 CTAs, 256 threads.
// ---------------------------------------------------------------------------
__global__ __launch_bounds__(256) void k_weights(const float* __restrict__ x)
{
    __shared__ float cent2[9*2*CH_STR];
    __shared__ float csq_s[9];

    int bid  = blockIdx.x;
    int b    = bid >> 9;
    int rem  = bid & 511;
    int blk  = rem >> 1;
    int half = rem & 1;
    int sy   = blk >> 4, sx = blk & 15;
    int tid  = threadIdx.x;

    stage_cent(g_cent1, cent2, csq_s, b, sy, sx, tid);

    int pl  = tid >> 1;
    int h   = tid & 1;
    int row = half*8 + (pl >> 4);
    int col = pl & 15;
    const float* xp = x + (size_t)b*CC*NPIX + (size_t)(h*32)*NPIX
                        + (size_t)(sy*SS + row)*WW + sx*SS + col;

    float p[32];
    #pragma unroll
    for (int i = 0; i < 32; i++) p[i] = xp[(size_t)i*NPIX];

    float dot[9];
    #pragma unroll
    for (int k = 0; k < 9; k++) dot[k] = 0.f;
    #pragma unroll
    for (int i = 0; i < 32; i++) {
        #pragma unroll
        for (int k = 0; k < 9; k++)
            dot[k] = fmaf(p[i], cent2[k*(2*CH_STR) + h*CH_STR + i], dot[k]);
    }
    #pragma unroll
    for (int k = 0; k < 9; k++)
        dot[k] += __shfl_xor_sync(0xffffffffu, dot[k], 1);

    float l[9];
    float m = -1e30f;
    #pragma unroll
    for (int k = 0; k < 9; k++) {
        int cy = sy + (k/3) - 1, cx = sx + (k%3) - 1;
        bool valid = (cy >= 0 && cy < NH && cx >= 0 && cx < NW);
        l[k] = valid ? (2.f*dot[k] - csq_s[k]) : -1e30f;
        m = fmaxf(m, l[k]);
    }
    float e[9], ssum = 0.f;
    #pragma unroll
    for (int k = 0; k < 9; k++) {
        e[k] = (l[k] > -1e29f) ? __expf(l[k] - m) : 0.f;
        ssum += e[k];
    }
    float inv = 1.f / ssum;

    // store: k<8 -> h==(k&1); k==8 -> h==0. 16 consecutive floats per warp-store.
    float* wp = g_w + ((size_t)(b*NSP + blk)*9)*256 + half*128 + pl;
    #pragma unroll
    for (int k = 0; k < 9; k++) {
        bool mine = (k < 8) ? (h == (k & 1)) : (h == 0);
        if (mine) wp[(size_t)k*256] = e[k]*inv;
    }
}

// ---------------------------------------------------------------------------
// K5: streaming output writer (writes all 134 MB exactly once, STG.128).
// grid = BB*NSP*4 = 2048 CTAs, block = 256.
// ---------------------------------------------------------------------------
__global__ __launch_bounds__(256) void k_write(float* __restrict__ out)
{
    int bid = blockIdx.x;
    int b   = bid >> 10;
    int rem = bid & 1023;
    int s   = rem >> 2;
    int q   = rem & 3;
    int sy  = s >> 4, sx = s & 15;
    int y0  = q * 64;

    float4* op = (float4*)(out + ((size_t)(b*NSP + s) << 16)) + (y0 << 6);
    const float4* wbase = (const float4*)g_w;

    int tid = threadIdx.x;
    #pragma unroll
    for (int it = 0; it < 16; it++) {
        int idx = it*256 + tid;
        int y   = y0 + (idx >> 6);
        int x4  = idx & 63;
        int by  = y >> 4;
        int bx  = x4 >> 2;
        int dy  = sy - by;
        int dx  = sx - bx;
        float4 v = make_float4(0.f, 0.f, 0.f, 0.f);
        if (dy >= -1 && dy <= 1 && dx >= -1 && dx <= 1) {
            int k   = (dy + 1)*3 + (dx + 1);
            int blk = by*NW + bx;
            int py  = y & 15;
            int px4 = x4 & 3;
            v = wbase[(((size_t)(b*NSP + blk)*9 + k) << 6) + (py << 2) + px4];
        }
        op[idx] = v;
    }
}

// ---------------------------------------------------------------------------
extern "C" void kernel_launch(void* const* d_in, const int* in_sizes, int n_in,
                              void* d_out, int out_size)
{
    const float* x = (const float*)d_in[0];
    float* out = (float*)d_out;

    k_means  <<<BB*CC*16,  256>>>(x);
    k_iter0  <<<BB*NSP*2,  256>>>(x);
    k_update <<<BB*NSP,     64>>>();
    k_weights<<<BB*NSP*2,  256>>>(x);
    k_write  <<<BB*NSP*4,  256>>>(out);
}

// round 6
// speedup vs baseline: 1.3783x; 1.0796x over previous
#include <cuda_runtime.h>

// Problem constants (fixed shapes: x = (2, 64, 256, 256) fp32, stoken_size = 16)
#define BB   2
#define CC   64
#define HH   256
#define WW   256
#define SS   16
#define NH   16
#define NW   16
#define NSP  256      // nH*nW
#define NPIX 65536    // H*W

// cent2 layout: [k][half][CH_STR], CH_STR=36 -> the two half-lanes' LDS banks
// differ by 4, so the 2-way broadcast read is bank-conflict-free.
#define CH_STR 36

// Scratch (device globals; no allocations allowed)
__device__ float g_cent0[BB*NSP*CC];
__device__ float g_cent1[BB*NSP*CC];
// per-(block,half) partials: [b][blk][half][k(9)][c(64)]
__device__ float g_part [BB*NSP*2*9*64];
// per-(block,half) weight sums: [b][blk][half][k(9)]
__device__ float g_den0 [BB*NSP*2*9];

// ---------------------------------------------------------------------------
// K1: zero-fill slice (32 KB/CTA, first half of out) + per-block channel means.
// CTA = (b, c, block-row by). 2048 CTAs, 256 threads, fully coalesced LDG.128.
// ---------------------------------------------------------------------------
__global__ __launch_bounds__(256) void k_means(const float* __restrict__ x,
                                               float* __restrict__ out)
{
    int tid = threadIdx.x;
    int bid = blockIdx.x;

    // fire-and-forget zero stores (no dependencies) — covers out[0 .. 67MB)
    {
        float4 z = make_float4(0.f, 0.f, 0.f, 0.f);
        float4* oz = (float4*)out + (size_t)bid*2048;
        #pragma unroll
        for (int j = 0; j < 8; j++) oz[j*256 + tid] = z;
    }

    int by  = bid & 15;
    int bc  = bid >> 4;          // b*64 + c
    int b   = bc >> 6, c = bc & 63;

    const float4* xp = (const float4*)(x + (size_t)bc*NPIX + (size_t)by*16*WW);
    int fc  = tid & 63;          // float4 column 0..63
    int g   = tid >> 6;          // row group 0..3

    float4 s = make_float4(0.f, 0.f, 0.f, 0.f);
    #pragma unroll
    for (int r = 0; r < 4; r++) {
        float4 v = xp[(g*4 + r)*64 + fc];
        s.x += v.x; s.y += v.y; s.z += v.z; s.w += v.w;
    }

    __shared__ float4 sm4[4][64];
    __shared__ float  smc[64];
    sm4[g][fc] = s;
    __syncthreads();

    if (tid < 64) {
        float4 a = sm4[0][tid], b4 = sm4[1][tid], c4 = sm4[2][tid], d4 = sm4[3][tid];
        smc[tid] = (a.x+a.y+a.z+a.w) + (b4.x+b4.y+b4.z+b4.w)
                 + (c4.x+c4.y+c4.z+c4.w) + (d4.x+d4.y+d4.z+d4.w);
    }
    __syncthreads();

    if (tid < 16) {
        float m = (smc[4*tid] + smc[4*tid+1] + smc[4*tid+2] + smc[4*tid+3]) * (1.f/256.f);
        g_cent0[((size_t)(b*NSP + by*16 + tid))*CC + c] = m;
    }
}

// ---------------------------------------------------------------------------
// Shared helper: stage 9 candidate centroids into cent2[k][h][CH_STR] + csq.
// ---------------------------------------------------------------------------
__device__ __forceinline__ void stage_cent(const float* __restrict__ cent,
                                           float* cent2, float* csq_s,
                                           int b, int sy, int sx, int tid)
{
    for (int i = tid; i < 9*64; i += 256) {
        int k = i >> 6, c = i & 63;
        int cy = sy + (k/3) - 1, cx = sx + (k%3) - 1;
        float v = 0.f;
        if (cy >= 0 && cy < NH && cx >= 0 && cx < NW)
            v = cent[((size_t)(b*NSP + cy*NW + cx))*CC + c];
        cent2[k*(2*CH_STR) + (c >> 5)*CH_STR + (c & 31)] = v;
    }
    __syncthreads();
    if (tid < 18) {
        int k = tid >> 1, h = tid & 1;
        float s = 0.f;
        #pragma unroll 8
        for (int c = 0; c < 32; c++) {
            float v = cent2[k*(2*CH_STR) + h*CH_STR + c];
            s = fmaf(v, v, s);
        }
        if (h == 0) csq_s[k] = s;
        __syncwarp(0x0003ffffu);
        if (h == 1) csq_s[k] += s;
    }
    __syncthreads();
}

// ---------------------------------------------------------------------------
// K2: zero-fill slice (64 KB/CTA, second half of out) + iteration 0 over
// HALF-blocks. CTA=(b,blk,half): 1024 CTAs, 256 threads.
// Thread = (pl 0..127 pixel-in-half, h 0..1 channel half). 32 LDGs/thread.
// ---------------------------------------------------------------------------
__global__ __launch_bounds__(256) void k_iter0(const float* __restrict__ x,
                                               float* __restrict__ out)
{
    __shared__ float cent2[9*2*CH_STR];
    __shared__ float csq_s[9];
    __shared__ float Wsh[128*9];
    __shared__ float dsm[8][9];

    int tid = threadIdx.x;
    int bid = blockIdx.x;

    // zero stores — covers out[67MB .. 134MB)
    {
        float4 z = make_float4(0.f, 0.f, 0.f, 0.f);
        float4* oz = (float4*)out + 4194304 + (size_t)bid*4096;
        #pragma unroll
        for (int j = 0; j < 16; j++) oz[j*256 + tid] = z;
    }

    int b    = bid >> 9;
    int rem  = bid & 511;
    int blk  = rem >> 1;
    int half = rem & 1;
    int sy   = blk >> 4, sx = blk & 15;

    stage_cent(g_cent0, cent2, csq_s, b, sy, sx, tid);

    // phase B
    int pl  = tid >> 1;                 // 0..127
    int h   = tid & 1;                  // channel half
    int row = half*8 + (pl >> 4);
    int col = pl & 15;
    const float* xp = x + (size_t)b*CC*NPIX + (size_t)(h*32)*NPIX
                        + (size_t)(sy*SS + row)*WW + sx*SS + col;

    float p[32];
    #pragma unroll
    for (int i = 0; i < 32; i++) p[i] = xp[(size_t)i*NPIX];

    float dot[9];
    #pragma unroll
    for (int k = 0; k < 9; k++) dot[k] = 0.f;
    #pragma unroll
    for (int i = 0; i < 32; i++) {
        #pragma unroll
        for (int k = 0; k < 9; k++)
            dot[k] = fmaf(p[i], cent2[k*(2*CH_STR) + h*CH_STR + i], dot[k]);
    }
    #pragma unroll
    for (int k = 0; k < 9; k++)
        dot[k] += __shfl_xor_sync(0xffffffffu, dot[k], 1);

    float l[9];
    float m = -1e30f;
    #pragma unroll
    for (int k = 0; k < 9; k++) {
        int cy = sy + (k/3) - 1, cx = sx + (k%3) - 1;
        bool valid = (cy >= 0 && cy < NH && cx >= 0 && cx < NW);
        l[k] = valid ? (2.f*dot[k] - csq_s[k]) : -1e30f;
        m = fmaxf(m, l[k]);
    }
    float e[9], ssum = 0.f;
    #pragma unroll
    for (int k = 0; k < 9; k++) {
        e[k] = (l[k] > -1e29f) ? __expf(l[k] - m) : 0.f;
        ssum += e[k];
    }
    float inv = 1.f / ssum;
    #pragma unroll
    for (int k = 0; k < 9; k++) e[k] *= inv;

    if (h == 0) {
        #pragma unroll
        for (int k = 0; k < 9; k++) Wsh[pl*9 + k] = e[k];
    }

    // per-half den[k]: each pixel counted twice across the 2 h-lanes -> *0.5
    {
        int wid = tid >> 5, lane = tid & 31;
        #pragma unroll
        for (int k = 0; k < 9; k++) {
            float v = e[k];
            #pragma unroll
            for (int o = 16; o > 0; o >>= 1) v += __shfl_xor_sync(0xffffffffu, v, o);
            if (lane == 0) dsm[wid][k] = v;
        }
        __syncthreads();
        if (tid < 9) {
            float s = 0.f;
            #pragma unroll
            for (int w = 0; w < 8; w++) s += dsm[w][tid];
            g_den0[((size_t)((b*NSP + blk)*2 + half))*9 + tid] = s * 0.5f;
        }
    }

    // phase C: warp wid -> channels [wid*8, wid*8+8) in 2 groups of 4.
    int wid = tid >> 5, lane = tid & 31;
    const float* xt = x + (size_t)b*CC*NPIX + (size_t)(sy*SS + half*8)*WW + sx*SS;
    float* pdst = g_part + ((size_t)((b*NSP + blk)*2 + half)*9)*64;

    #pragma unroll
    for (int grp = 0; grp < 2; grp++) {
        int cbase = wid*8 + grp*4;
        float acc[4][9];
        #pragma unroll
        for (int cc = 0; cc < 4; cc++)
            #pragma unroll
            for (int k = 0; k < 9; k++) acc[cc][k] = 0.f;

        #pragma unroll
        for (int j = 0; j < 4; j++) {
            int pix = j*32 + lane;                // 0..127 within half
            int prow = pix >> 4, pcol = pix & 15;
            float w[9];
            #pragma unroll
            for (int k = 0; k < 9; k++) w[k] = Wsh[pix*9 + k];
            #pragma unroll
            for (int cc = 0; cc < 4; cc++) {
                float pv = xt[(size_t)(cbase + cc)*NPIX + prow*WW + pcol];
                #pragma unroll
                for (int k = 0; k < 9; k++) acc[cc][k] = fmaf(w[k], pv, acc[cc][k]);
            }
        }
        #pragma unroll
        for (int cc = 0; cc < 4; cc++)
            #pragma unroll
            for (int k = 0; k < 9; k++)
                #pragma unroll
                for (int o = 16; o > 0; o >>= 1)
                    acc[cc][k] += __shfl_xor_sync(0xffffffffu, acc[cc][k], o);
        #pragma unroll
        for (int k = 0; k < 9; k++) {
            if (lane == k) {
                #pragma unroll
                for (int cc = 0; cc < 4; cc++)
                    pdst[(size_t)k*64 + cbase + cc] = acc[cc][k];
            }
        }
    }
}

// ---------------------------------------------------------------------------
// K3: gather per-superpixel centroid update (no atomics).
// grid = 512 (b,s), block = 64 (one thread per channel).
// ---------------------------------------------------------------------------
__global__ __launch_bounds__(64) void k_update()
{
    int bid = blockIdx.x;
    int b   = bid >> 8;
    int s   = bid & 255;
    int sy  = s >> 4, sx = s & 15;
    int c   = threadIdx.x;

    __shared__ float dsm[9];
    if (c < 9) {
        int dy = c/3 - 1, dx = c%3 - 1;
        int ny = sy + dy, nx = sx + dx;
        float d = 0.f;
        if (ny >= 0 && ny < NH && nx >= 0 && nx < NW) {
            int nb = ny*NW + nx;
            d = g_den0[((size_t)((b*NSP + nb)*2 + 0))*9 + (8 - c)]
              + g_den0[((size_t)((b*NSP + nb)*2 + 1))*9 + (8 - c)];
        }
        dsm[c] = d;
    }
    __syncthreads();

    float den = 0.f;
    #pragma unroll
    for (int j = 0; j < 9; j++) den += dsm[j];

    float num = 0.f;
    #pragma unroll
    for (int j = 0; j < 9; j++) {
        int dy = j/3 - 1, dx = j%3 - 1;
        int ny = sy + dy, nx = sx + dx;
        if (ny >= 0 && ny < NH && nx >= 0 && nx < NW) {
            int nb = ny*NW + nx;
            num += g_part[((size_t)((b*NSP + nb)*2 + 0)*9 + (8 - j))*64 + c]
                 + g_part[((size_t)((b*NSP + nb)*2 + 1)*9 + (8 - j))*64 + c];
        }
    }
    g_cent1[((size_t)(b*NSP + s))*CC + c] = num / (den + 1e-16f);
}

// ---------------------------------------------------------------------------
// K4: final weights over HALF-blocks, scattered directly into the pre-zeroed
// output: out[b][cand_k][n] = w[k]. 1024 CTAs, 256 threads.
// Per k, a half-warp stores 16 consecutive floats (sector-aligned 64 B).
// ---------------------------------------------------------------------------
__global__ __launch_bounds__(256) void k_final(const float* __restrict__ x,
                                               float* __restrict__ out)
{
    __shared__ float cent2[9*2*CH_STR];
    __shared__ float csq_s[9];

    int bid  = blockIdx.x;
    int b    = bid >> 9;
    int rem  = bid & 511;
    int blk  = rem >> 1;
    int half = rem & 1;
    int sy   = blk >> 4, sx = blk & 15;
    int tid  = threadIdx.x;

    stage_cent(g_cent1, cent2, csq_s, b, sy, sx, tid);

    int pl  = tid >> 1;
    int h   = tid & 1;
    int row = half*8 + (pl >> 4);
    int col = pl & 15;
    int n   = (sy*SS + row)*WW + sx*SS + col;
    const float* xp = x + (size_t)b*CC*NPIX + (size_t)(h*32)*NPIX + n;

    float p[32];
    #pragma unroll
    for (int i = 0; i < 32; i++) p[i] = xp[(size_t)i*NPIX];

    float dot[9];
    #pragma unroll
    for (int k = 0; k < 9; k++) dot[k] = 0.f;
    #pragma unroll
    for (int i = 0; i < 32; i++) {
        #pragma unroll
        for (int k = 0; k < 9; k++)
            dot[k] = fmaf(p[i], cent2[k*(2*CH_STR) + h*CH_STR + i], dot[k]);
    }
    #pragma unroll
    for (int k = 0; k < 9; k++)
        dot[k] += __shfl_xor_sync(0xffffffffu, dot[k], 1);

    float l[9];
    float m = -1e30f;
    #pragma unroll
    for (int k = 0; k < 9; k++) {
        int cy = sy + (k/3) - 1, cx = sx + (k%3) - 1;
        bool valid = (cy >= 0 && cy < NH && cx >= 0 && cx < NW);
        l[k] = valid ? (2.f*dot[k] - csq_s[k]) : -1e30f;
        m = fmaxf(m, l[k]);
    }
    float e[9], ssum = 0.f;
    #pragma unroll
    for (int k = 0; k < 9; k++) {
        e[k] = (l[k] > -1e29f) ? __expf(l[k] - m) : 0.f;
        ssum += e[k];
    }
    float inv = 1.f / ssum;

    float* obase = out + ((size_t)b*NSP << 16);
    #pragma unroll
    for (int k = 0; k < 9; k++) {
        int cy = sy + (k/3) - 1, cx = sx + (k%3) - 1;
        bool valid = (cy >= 0 && cy < NH && cx >= 0 && cx < NW);
        bool mine  = (k < 8) ? (h == (k & 1)) : (h == 0);
        if (valid && mine) {
            obase[((size_t)(cy*NW + cx) << 16) + n] = e[k]*inv;
        }
    }
}

// ---------------------------------------------------------------------------
extern "C" void kernel_launch(void* const* d_in, const int* in_sizes, int n_in,
                              void* d_out, int out_size)
{
    const float* x = (const float*)d_in[0];
    float* out = (float*)d_out;

    k_means  <<<BB*CC*16,  256>>>(x, out);
    k_iter0  <<<BB*NSP*2,  256>>>(x, out);
    k_update <<<BB*NSP,     64>>>();
    k_final  <<<BB*NSP*2,  256>>>(x, out);
}

// round 7
// speedup vs baseline: 1.3844x; 1.0044x over previous
#include <cuda_runtime.h>

// Problem constants (fixed shapes: x = (2, 64, 256, 256) fp32, stoken_size = 16)
#define BB   2
#define CC   64
#define HH   256
#define WW   256
#define SS   16
#define NH   16
#define NW   16
#define NSP  256      // nH*nW
#define NPIX 65536    // H*W

// cent2 float layout: [k][half][36]; as float4: [k][half][9] (8 used + 1 pad).
// The two half-lanes' float4 addresses differ by 9 float4 = banks disjoint.
#define CH_STR 36

// Scratch (device globals; no allocations allowed)
__device__ float g_cent0[BB*NSP*CC];
__device__ float g_cent1[BB*NSP*CC];
// per-(block,half) partials: [b][blk][half][k(9)][c(64)]
__device__ float g_part [BB*NSP*2*9*64];
// per-(block,half) weight sums: [b][blk][half][k(9)]
__device__ float g_den0 [BB*NSP*2*9];

// ---------------------------------------------------------------------------
// K1: zero-fill slice (32 KB/CTA, first half of out) + per-block channel means.
// CTA = (b, c, block-row by). 2048 CTAs, 256 threads, fully coalesced LDG.128.
// ---------------------------------------------------------------------------
__global__ __launch_bounds__(256) void k_means(const float* __restrict__ x,
                                               float* __restrict__ out)
{
    int tid = threadIdx.x;
    int bid = blockIdx.x;

    // fire-and-forget zero stores — covers out[0 .. 67MB)
    {
        float4 z = make_float4(0.f, 0.f, 0.f, 0.f);
        float4* oz = (float4*)out + (size_t)bid*2048;
        #pragma unroll
        for (int j = 0; j < 8; j++) oz[j*256 + tid] = z;
    }

    int by  = bid & 15;
    int bc  = bid >> 4;          // b*64 + c
    int b   = bc >> 6, c = bc & 63;

    const float4* xp = (const float4*)(x + (size_t)bc*NPIX + (size_t)by*16*WW);
    int fc  = tid & 63;          // float4 column 0..63
    int g   = tid >> 6;          // row group 0..3

    float4 s = make_float4(0.f, 0.f, 0.f, 0.f);
    #pragma unroll
    for (int r = 0; r < 4; r++) {
        float4 v = xp[(g*4 + r)*64 + fc];
        s.x += v.x; s.y += v.y; s.z += v.z; s.w += v.w;
    }

    __shared__ float4 sm4[4][64];
    __shared__ float  smc[64];
    sm4[g][fc] = s;
    __syncthreads();

    if (tid < 64) {
        float4 a = sm4[0][tid], b4 = sm4[1][tid], c4 = sm4[2][tid], d4 = sm4[3][tid];
        smc[tid] = (a.x+a.y+a.z+a.w) + (b4.x+b4.y+b4.z+b4.w)
                 + (c4.x+c4.y+c4.z+c4.w) + (d4.x+d4.y+d4.z+d4.w);
    }
    __syncthreads();

    if (tid < 16) {
        float m = (smc[4*tid] + smc[4*tid+1] + smc[4*tid+2] + smc[4*tid+3]) * (1.f/256.f);
        g_cent0[((size_t)(b*NSP + by*16 + tid))*CC + c] = m;
    }
}

// ---------------------------------------------------------------------------
// Shared helper: stage 9 candidate centroids into cent2[k][h][CH_STR] + csq.
// ---------------------------------------------------------------------------
__device__ __forceinline__ void stage_cent(const float* __restrict__ cent,
                                           float* cent2, float* csq_s,
                                           int b, int sy, int sx, int tid)
{
    for (int i = tid; i < 9*64; i += 256) {
        int k = i >> 6, c = i & 63;
        int cy = sy + (k/3) - 1, cx = sx + (k%3) - 1;
        float v = 0.f;
        if (cy >= 0 && cy < NH && cx >= 0 && cx < NW)
            v = cent[((size_t)(b*NSP + cy*NW + cx))*CC + c];
        cent2[k*(2*CH_STR) + (c >> 5)*CH_STR + (c & 31)] = v;
    }
    __syncthreads();
    if (tid < 18) {
        int k = tid >> 1, h = tid & 1;
        float s = 0.f;
        #pragma unroll 8
        for (int c = 0; c < 32; c++) {
            float v = cent2[k*(2*CH_STR) + h*CH_STR + c];
            s = fmaf(v, v, s);
        }
        if (h == 0) csq_s[k] = s;
        __syncwarp(0x0003ffffu);
        if (h == 1) csq_s[k] += s;
    }
    __syncthreads();
}

// ---------------------------------------------------------------------------
// Shared helper: per-thread dots via float4 LDS (72 LDS.128 instead of 288
// LDS.32). cv addresses per warp: 2 distinct float4 slots, bank-disjoint.
// ---------------------------------------------------------------------------
__device__ __forceinline__ void dot9(const float* p, const float4* cent4,
                                     int h, float* dot)
{
    #pragma unroll
    for (int k = 0; k < 9; k++) dot[k] = 0.f;
    #pragma unroll
    for (int i4 = 0; i4 < 8; i4++) {
        float4 pv = ((const float4*)p)[i4];
        #pragma unroll
        for (int k = 0; k < 9; k++) {
            float4 cv = cent4[k*18 + h*9 + i4];
            dot[k] = fmaf(pv.x, cv.x, dot[k]);
            dot[k] = fmaf(pv.y, cv.y, dot[k]);
            dot[k] = fmaf(pv.z, cv.z, dot[k]);
            dot[k] = fmaf(pv.w, cv.w, dot[k]);
        }
    }
    #pragma unroll
    for (int k = 0; k < 9; k++)
        dot[k] += __shfl_xor_sync(0xffffffffu, dot[k], 1);
}

// ---------------------------------------------------------------------------
// K2: zero-fill slice (64 KB/CTA, second half of out) + iteration 0 over
// HALF-blocks. CTA=(b,blk,half): 1024 CTAs, 256 threads.
// ---------------------------------------------------------------------------
__global__ __launch_bounds__(256) void k_iter0(const float* __restrict__ x,
                                               float* __restrict__ out)
{
    __shared__ __align__(16) float cent2[9*2*CH_STR];
    __shared__ float csq_s[9];
    __shared__ float Wsh[128*9];
    __shared__ float dsm[8][9];

    int tid = threadIdx.x;
    int bid = blockIdx.x;

    // zero stores — covers out[67MB .. 134MB)
    {
        float4 z = make_float4(0.f, 0.f, 0.f, 0.f);
        float4* oz = (float4*)out + 4194304 + (size_t)bid*4096;
        #pragma unroll
        for (int j = 0; j < 16; j++) oz[j*256 + tid] = z;
    }

    int b    = bid >> 9;
    int rem  = bid & 511;
    int blk  = rem >> 1;
    int half = rem & 1;
    int sy   = blk >> 4, sx = blk & 15;

    stage_cent(g_cent0, cent2, csq_s, b, sy, sx, tid);

    // phase B
    int pl  = tid >> 1;                 // 0..127
    int h   = tid & 1;                  // channel half
    int row = half*8 + (pl >> 4);
    int col = pl & 15;
    const float* xp = x + (size_t)b*CC*NPIX + (size_t)(h*32)*NPIX
                        + (size_t)(sy*SS + row)*WW + sx*SS + col;

    float p[32];
    #pragma unroll
    for (int i = 0; i < 32; i++) p[i] = xp[(size_t)i*NPIX];

    float dot[9];
    dot9(p, (const float4*)cent2, h, dot);

    float l[9];
    float m = -1e30f;
    #pragma unroll
    for (int k = 0; k < 9; k++) {
        int cy = sy + (k/3) - 1, cx = sx + (k%3) - 1;
        bool valid = (cy >= 0 && cy < NH && cx >= 0 && cx < NW);
        l[k] = valid ? (2.f*dot[k] - csq_s[k]) : -1e30f;
        m = fmaxf(m, l[k]);
    }
    float e[9], ssum = 0.f;
    #pragma unroll
    for (int k = 0; k < 9; k++) {
        e[k] = (l[k] > -1e29f) ? __expf(l[k] - m) : 0.f;
        ssum += e[k];
    }
    float inv = 1.f / ssum;
    #pragma unroll
    for (int k = 0; k < 9; k++) e[k] *= inv;

    if (h == 0) {
        #pragma unroll
        for (int k = 0; k < 9; k++) Wsh[pl*9 + k] = e[k];
    }

    // per-half den[k]: each pixel counted twice across the 2 h-lanes -> *0.5
    {
        int wid = tid >> 5, lane = tid & 31;
        #pragma unroll
        for (int k = 0; k < 9; k++) {
            float v = e[k];
            #pragma unroll
            for (int o = 16; o > 0; o >>= 1) v += __shfl_xor_sync(0xffffffffu, v, o);
            if (lane == 0) dsm[wid][k] = v;
        }
        __syncthreads();
        if (tid < 9) {
            float s = 0.f;
            #pragma unroll
            for (int w = 0; w < 8; w++) s += dsm[w][tid];
            g_den0[((size_t)((b*NSP + blk)*2 + half))*9 + tid] = s * 0.5f;
        }
    }

    // phase C: warp wid -> channels [wid*8, wid*8+8) in 2 groups of 4.
    int wid = tid >> 5, lane = tid & 31;
    const float* xt = x + (size_t)b*CC*NPIX + (size_t)(sy*SS + half*8)*WW + sx*SS;
    float* pdst = g_part + ((size_t)((b*NSP + blk)*2 + half)*9)*64;

    #pragma unroll
    for (int grp = 0; grp < 2; grp++) {
        int cbase = wid*8 + grp*4;
        float acc[4][9];
        #pragma unroll
        for (int cc = 0; cc < 4; cc++)
            #pragma unroll
            for (int k = 0; k < 9; k++) acc[cc][k] = 0.f;

        #pragma unroll
        for (int j = 0; j < 4; j++) {
            int pix = j*32 + lane;                // 0..127 within half
            int prow = pix >> 4, pcol = pix & 15;
            float w[9];
            #pragma unroll
            for (int k = 0; k < 9; k++) w[k] = Wsh[pix*9 + k];
            #pragma unroll
            for (int cc = 0; cc < 4; cc++) {
                float pv = xt[(size_t)(cbase + cc)*NPIX + prow*WW + pcol];
                #pragma unroll
                for (int k = 0; k < 9; k++) acc[cc][k] = fmaf(w[k], pv, acc[cc][k]);
            }
        }
        #pragma unroll
        for (int cc = 0; cc < 4; cc++)
            #pragma unroll
            for (int k = 0; k < 9; k++)
                #pragma unroll
                for (int o = 16; o > 0; o >>= 1)
                    acc[cc][k] += __shfl_xor_sync(0xffffffffu, acc[cc][k], o);
        #pragma unroll
        for (int k = 0; k < 9; k++) {
            if (lane == k) {
                #pragma unroll
                for (int cc = 0; cc < 4; cc++)
                    pdst[(size_t)k*64 + cbase + cc] = acc[cc][k];
            }
        }
    }
}

// ---------------------------------------------------------------------------
// K3: gather per-superpixel centroid update (no atomics).
// grid = 512 (b,s), block = 128: thread = (channel, half); 9-load chain per
// thread then one shfl merge (halves the serialized latency chain).
// ---------------------------------------------------------------------------
__global__ __launch_bounds__(128) void k_update()
{
    int bid = blockIdx.x;
    int b   = bid >> 8;
    int s   = bid & 255;
    int sy  = s >> 4, sx = s & 15;
    int tid = threadIdx.x;
    int c   = tid >> 1;
    int hf  = tid & 1;

    __shared__ float dsm[9];
    if (tid < 18) {
        int j = tid >> 1, dh = tid & 1;
        int dy = j/3 - 1, dx = j%3 - 1;
        int ny = sy + dy, nx = sx + dx;
        float d = 0.f;
        if (ny >= 0 && ny < NH && nx >= 0 && nx < NW) {
            int nb = ny*NW + nx;
            d = g_den0[((size_t)((b*NSP + nb)*2 + dh))*9 + (8 - j)];
        }
        if (dh == 0) dsm[j] = d;
        __syncwarp(0x0003ffffu);
        if (dh == 1) dsm[j] += d;
    }

    float num = 0.f;
    #pragma unroll
    for (int j = 0; j < 9; j++) {
        int dy = j/3 - 1, dx = j%3 - 1;
        int ny = sy + dy, nx = sx + dx;
        if (ny >= 0 && ny < NH && nx >= 0 && nx < NW) {
            int nb = ny*NW + nx;
            num += g_part[((size_t)((b*NSP + nb)*2 + hf)*9 + (8 - j))*64 + c];
        }
    }
    num += __shfl_xor_sync(0xffffffffu, num, 1);
    __syncthreads();

    if (hf == 0) {
        float den = 0.f;
        #pragma unroll
        for (int j = 0; j < 9; j++) den += dsm[j];
        g_cent1[((size_t)(b*NSP + s))*CC + c] = num / (den + 1e-16f);
    }
}

// ---------------------------------------------------------------------------
// K4: final weights over HALF-blocks, scattered directly into the pre-zeroed
// output. 1024 CTAs, 256 threads.
// ---------------------------------------------------------------------------
__global__ __launch_bounds__(256) void k_final(const float* __restrict__ x,
                                               float* __restrict__ out)
{
    __shared__ __align__(16) float cent2[9*2*CH_STR];
    __shared__ float csq_s[9];

    int bid  = blockIdx.x;
    int b    = bid >> 9;
    int rem  = bid & 511;
    int blk  = rem >> 1;
    int half = rem & 1;
    int sy   = blk >> 4, sx = blk & 15;
    int tid  = threadIdx.x;

    stage_cent(g_cent1, cent2, csq_s, b, sy, sx, tid);

    int pl  = tid >> 1;
    int h   = tid & 1;
    int row = half*8 + (pl >> 4);
    int col = pl & 15;
    int n   = (sy*SS + row)*WW + sx*SS + col;
    const float* xp = x + (size_t)b*CC*NPIX + (size_t)(h*32)*NPIX + n;

    float p[32];
    #pragma unroll
    for (int i = 0; i < 32; i++) p[i] = xp[(size_t)i*NPIX];

    float dot[9];
    dot9(p, (const float4*)cent2, h, dot);

    float l[9];
    float m = -1e30f;
    #pragma unroll
    for (int k = 0; k < 9; k++) {
        int cy = sy + (k/3) - 1, cx = sx + (k%3) - 1;
        bool valid = (cy >= 0 && cy < NH && cx >= 0 && cx < NW);
        l[k] = valid ? (2.f*dot[k] - csq_s[k]) : -1e30f;
        m = fmaxf(m, l[k]);
    }
    float e[9], ssum = 0.f;
    #pragma unroll
    for (int k = 0; k < 9; k++) {
        e[k] = (l[k] > -1e29f) ? __expf(l[k] - m) : 0.f;
        ssum += e[k];
    }
    float inv = 1.f / ssum;

    float* obase = out + ((size_t)b*NSP << 16);
    #pragma unroll
    for (int k = 0; k < 9; k++) {
        int cy = sy + (k/3) - 1, cx = sx + (k%3) - 1;
        bool valid = (cy >= 0 && cy < NH && cx >= 0 && cx < NW);
        bool mine  = (k < 8) ? (h == (k & 1)) : (h == 0);
        if (valid && mine) {
            obase[((size_t)(cy*NW + cx) << 16) + n] = e[k]*inv;
        }
    }
}

// ---------------------------------------------------------------------------
extern "C" void kernel_launch(void* const* d_in, const int* in_sizes, int n_in,
                              void* d_out, int out_size)
{
    const float* x = (const float*)d_in[0];
    float* out = (float*)d_out;

    k_means  <<<BB*CC*16,  256>>>(x, out);
    k_iter0  <<<BB*NSP*2,  256>>>(x, out);
    k_update <<<BB*NSP,    128>>>();
    k_final  <<<BB*NSP*2,  256>>>(x, out);
}

// round 8
// speedup vs baseline: 1.4591x; 1.0540x over previous
#include <cuda_runtime.h>

// Problem constants (fixed shapes: x = (2, 64, 256, 256) fp32, stoken_size = 16)
#define BB   2
#define CC   64
#define HH   256
#define WW   256
#define SS   16
#define NH   16
#define NW   16
#define NSP  256      // nH*nW
#define NPIX 65536    // H*W

// cent2 float layout: [k][half][36]; as float4: [k][18] (h*9 + 8 used + pad).
#define CH_STR 36

// Scratch (device globals; no allocations allowed)
__device__ float g_cent0[BB*NSP*CC];
__device__ float g_cent1[BB*NSP*CC];
// per-block partials: [b][blk][k(9)][c(64)]
__device__ float g_part [BB*NSP*9*64];
// per-block weight sums: [b][blk][k(9)]
__device__ float g_den0 [BB*NSP*9];

// ---------------------------------------------------------------------------
// K1: zero-fill (75% of out, 48KB/CTA) + per-block channel means.
// CTA = (b, c, block-row by). 2048 CTAs, 256 threads, fully coalesced LDG.128.
// ---------------------------------------------------------------------------
__global__ __launch_bounds__(256) void k_means(const float* __restrict__ x,
                                               float* __restrict__ out)
{
    int tid = threadIdx.x;
    int bid = blockIdx.x;

    // fire-and-forget zero stores — covers out4[0 .. 6291456)
    {
        float4 z = make_float4(0.f, 0.f, 0.f, 0.f);
        float4* oz = (float4*)out + (size_t)bid*3072;
        #pragma unroll
        for (int j = 0; j < 12; j++) oz[j*256 + tid] = z;
    }

    int by  = bid & 15;
    int bc  = bid >> 4;          // b*64 + c
    int b   = bc >> 6, c = bc & 63;

    const float4* xp = (const float4*)(x + (size_t)bc*NPIX + (size_t)by*16*WW);
    int fc  = tid & 63;          // float4 column 0..63
    int g   = tid >> 6;          // row group 0..3

    float4 s = make_float4(0.f, 0.f, 0.f, 0.f);
    #pragma unroll
    for (int r = 0; r < 4; r++) {
        float4 v = xp[(g*4 + r)*64 + fc];
        s.x += v.x; s.y += v.y; s.z += v.z; s.w += v.w;
    }

    __shared__ float4 sm4[4][64];
    __shared__ float  smc[64];
    sm4[g][fc] = s;
    __syncthreads();

    if (tid < 64) {
        float4 a = sm4[0][tid], b4 = sm4[1][tid], c4 = sm4[2][tid], d4 = sm4[3][tid];
        smc[tid] = (a.x+a.y+a.z+a.w) + (b4.x+b4.y+b4.z+b4.w)
                 + (c4.x+c4.y+c4.z+c4.w) + (d4.x+d4.y+d4.z+d4.w);
    }
    __syncthreads();

    if (tid < 16) {
        float m = (smc[4*tid] + smc[4*tid+1] + smc[4*tid+2] + smc[4*tid+3]) * (1.f/256.f);
        g_cent0[((size_t)(b*NSP + by*16 + tid))*CC + c] = m;
    }
}

// ---------------------------------------------------------------------------
// Shared helper: stage 9 candidate centroids into cent2[k][h][CH_STR] + csq.
// ---------------------------------------------------------------------------
__device__ __forceinline__ void stage_cent(const float* __restrict__ cent,
                                           float* cent2, float* csq_s,
                                           int b, int sy, int sx, int tid)
{
    for (int i = tid; i < 9*64; i += 256) {
        int k = i >> 6, c = i & 63;
        int cy = sy + (k/3) - 1, cx = sx + (k%3) - 1;
        float v = 0.f;
        if (cy >= 0 && cy < NH && cx >= 0 && cx < NW)
            v = cent[((size_t)(b*NSP + cy*NW + cx))*CC + c];
        cent2[k*(2*CH_STR) + (c >> 5)*CH_STR + (c & 31)] = v;
    }
    __syncthreads();
    if (tid < 18) {
        int k = tid >> 1, h = tid & 1;
        float s = 0.f;
        #pragma unroll 8
        for (int c = 0; c < 32; c++) {
            float v = cent2[k*(2*CH_STR) + h*CH_STR + c];
            s = fmaf(v, v, s);
        }
        if (h == 0) csq_s[k] = s;
        __syncwarp(0x0003ffffu);
        if (h == 1) csq_s[k] += s;
    }
    __syncthreads();
}

// ---------------------------------------------------------------------------
// Shared helper: pixel-pair dots. Thread covers 2 pixels (float2 loads) x 32
// channels (half h). 32 LDG.64 + 72 LDS.128 + 576 FMA, 2 indep. FMA chains
// per load. Then merge halves via shfl.
// ---------------------------------------------------------------------------
__device__ __forceinline__ void dot9p(const float* xp, const float4* cent4,
                                      int h, float acc[2][9])
{
    #pragma unroll
    for (int k = 0; k < 9; k++) { acc[0][k] = 0.f; acc[1][k] = 0.f; }

    #pragma unroll
    for (int c8 = 0; c8 < 4; c8++) {
        float2 p[8];
        #pragma unroll
        for (int i = 0; i < 8; i++)
            p[i] = *(const float2*)(xp + (size_t)(c8*8 + i)*NPIX);
        #pragma unroll
        for (int g = 0; g < 2; g++) {
            #pragma unroll
            for (int k = 0; k < 9; k++) {
                float4 cv = cent4[k*18 + h*9 + c8*2 + g];
                acc[0][k] = fmaf(p[g*4+0].x, cv.x, acc[0][k]);
                acc[1][k] = fmaf(p[g*4+0].y, cv.x, acc[1][k]);
                acc[0][k] = fmaf(p[g*4+1].x, cv.y, acc[0][k]);
                acc[1][k] = fmaf(p[g*4+1].y, cv.y, acc[1][k]);
                acc[0][k] = fmaf(p[g*4+2].x, cv.z, acc[0][k]);
                acc[1][k] = fmaf(p[g*4+2].y, cv.z, acc[1][k]);
                acc[0][k] = fmaf(p[g*4+3].x, cv.w, acc[0][k]);
                acc[1][k] = fmaf(p[g*4+3].y, cv.w, acc[1][k]);
            }
        }
    }
    #pragma unroll
    for (int k = 0; k < 9; k++) {
        acc[0][k] += __shfl_xor_sync(0xffffffffu, acc[0][k], 1);
        acc[1][k] += __shfl_xor_sync(0xffffffffu, acc[1][k], 1);
    }
}

// ---------------------------------------------------------------------------
// Shared helper: softmax for this thread's pixel (lane h owns pixel pp*2+h).
// Returns normalized weights in e[9].
// ---------------------------------------------------------------------------
__device__ __forceinline__ void softmax9(const float* dot, const float* csq_s,
                                         int sy, int sx, float* e)
{
    float l[9];
    float m = -1e30f;
    #pragma unroll
    for (int k = 0; k < 9; k++) {
        int cy = sy + (k/3) - 1, cx = sx + (k%3) - 1;
        bool valid = (cy >= 0 && cy < NH && cx >= 0 && cx < NW);
        l[k] = valid ? (2.f*dot[k] - csq_s[k]) : -1e30f;
        m = fmaxf(m, l[k]);
    }
    float ssum = 0.f;
    #pragma unroll
    for (int k = 0; k < 9; k++) {
        e[k] = (l[k] > -1e29f) ? __expf(l[k] - m) : 0.f;
        ssum += e[k];
    }
    float inv = 1.f / ssum;
    #pragma unroll
    for (int k = 0; k < 9; k++) e[k] *= inv;
}

// ---------------------------------------------------------------------------
// K2: zero-fill (25% of out, 64KB/CTA) + iteration 0 over FULL blocks.
// 512 CTAs, 256 threads: thread = (pp 0..127, h 0..1).
// Phase B: pixel-pair dots + softmax -> Wsh[256][9] + den. Phase C: partials.
// ---------------------------------------------------------------------------
__global__ __launch_bounds__(256) void k_iter0(const float* __restrict__ x,
                                               float* __restrict__ out)
{
    __shared__ __align__(16) float cent2[9*2*CH_STR];
    __shared__ float csq_s[9];
    __shared__ float Wsh[256*9];
    __shared__ float dsm[8][9];

    int tid = threadIdx.x;
    int bid = blockIdx.x;

    // zero stores — covers out4[6291456 .. 8388608)
    {
        float4 z = make_float4(0.f, 0.f, 0.f, 0.f);
        float4* oz = (float4*)out + 6291456 + (size_t)bid*4096;
        #pragma unroll
        for (int j = 0; j < 16; j++) oz[j*256 + tid] = z;
    }

    int b   = bid >> 8;
    int blk = bid & 255;
    int sy  = blk >> 4, sx = blk & 15;

    stage_cent(g_cent0, cent2, csq_s, b, sy, sx, tid);

    // phase B
    int pp  = tid >> 1;                 // pixel pair 0..127
    int h   = tid & 1;                  // channel half
    int row = pp >> 3;
    int col2= (pp & 7)*2;
    int n0  = (sy*SS + row)*WW + sx*SS + col2;
    const float* xp = x + (size_t)b*CC*NPIX + (size_t)(h*32)*NPIX + n0;

    float acc[2][9];
    dot9p(xp, (const float4*)cent2, h, acc);

    int pix = pp*2 + h;                 // this thread's pixel
    float e[9];
    softmax9(acc[h], csq_s, sy, sx, e);

    #pragma unroll
    for (int k = 0; k < 9; k++) Wsh[pix*9 + k] = e[k];

    // den[k] over all 256 pixels (each lane owns a distinct pixel)
    {
        int wid = tid >> 5, lane = tid & 31;
        #pragma unroll
        for (int k = 0; k < 9; k++) {
            float v = e[k];
            #pragma unroll
            for (int o = 16; o > 0; o >>= 1) v += __shfl_xor_sync(0xffffffffu, v, o);
            if (lane == 0) dsm[wid][k] = v;
        }
        __syncthreads();
        if (tid < 9) {
            float s = 0.f;
            #pragma unroll
            for (int w = 0; w < 8; w++) s += dsm[w][tid];
            g_den0[((size_t)(b*NSP + blk))*9 + tid] = s;
        }
    }

    // phase C: warp wid -> channels [wid*8, wid*8+8) in 2 groups of 4.
    int wid = tid >> 5, lane = tid & 31;
    const float* xt = x + (size_t)b*CC*NPIX + (size_t)(sy*SS)*WW + sx*SS;
    float* pdst = g_part + ((size_t)(b*NSP + blk)*9)*64;

    #pragma unroll
    for (int grp = 0; grp < 2; grp++) {
        int cbase = wid*8 + grp*4;
        float pacc[4][9];
        #pragma unroll
        for (int cc = 0; cc < 4; cc++)
            #pragma unroll
            for (int k = 0; k < 9; k++) pacc[cc][k] = 0.f;

        #pragma unroll
        for (int j = 0; j < 8; j++) {
            int px = j*32 + lane;
            int prow = px >> 4, pcol = px & 15;
            float w[9];
            #pragma unroll
            for (int k = 0; k < 9; k++) w[k] = Wsh[px*9 + k];
            #pragma unroll
            for (int cc = 0; cc < 4; cc++) {
                float pv = xt[(size_t)(cbase + cc)*NPIX + prow*WW + pcol];
                #pragma unroll
                for (int k = 0; k < 9; k++) pacc[cc][k] = fmaf(w[k], pv, pacc[cc][k]);
            }
        }
        #pragma unroll
        for (int cc = 0; cc < 4; cc++)
            #pragma unroll
            for (int k = 0; k < 9; k++)
                #pragma unroll
                for (int o = 16; o > 0; o >>= 1)
                    pacc[cc][k] += __shfl_xor_sync(0xffffffffu, pacc[cc][k], o);
        #pragma unroll
        for (int k = 0; k < 9; k++) {
            if (lane == k) {
                #pragma unroll
                for (int cc = 0; cc < 4; cc++)
                    pdst[(size_t)k*64 + cbase + cc] = pacc[cc][k];
            }
        }
    }
}

// ---------------------------------------------------------------------------
// K3: gather per-superpixel centroid update (no atomics).
// grid = 512 (b,s), block = 64 (one thread per channel).
// ---------------------------------------------------------------------------
__global__ __launch_bounds__(64) void k_update()
{
    int bid = blockIdx.x;
    int b   = bid >> 8;
    int s   = bid & 255;
    int sy  = s >> 4, sx = s & 15;
    int c   = threadIdx.x;

    __shared__ float dsm[9];
    if (c < 9) {
        int dy = c/3 - 1, dx = c%3 - 1;
        int ny = sy + dy, nx = sx + dx;
        float d = 0.f;
        if (ny >= 0 && ny < NH && nx >= 0 && nx < NW)
            d = g_den0[((size_t)(b*NSP + ny*NW + nx))*9 + (8 - c)];
        dsm[c] = d;
    }
    __syncthreads();

    float den = 0.f;
    #pragma unroll
    for (int j = 0; j < 9; j++) den += dsm[j];

    float num = 0.f;
    #pragma unroll
    for (int j = 0; j < 9; j++) {
        int dy = j/3 - 1, dx = j%3 - 1;
        int ny = sy + dy, nx = sx + dx;
        if (ny >= 0 && ny < NH && nx >= 0 && nx < NW)
            num += g_part[((size_t)((b*NSP + ny*NW + nx)*9 + (8 - j)))*64 + c];
    }
    g_cent1[((size_t)(b*NSP + s))*CC + c] = num / (den + 1e-16f);
}

// ---------------------------------------------------------------------------
// K4: final weights over FULL blocks, scattered into the pre-zeroed output.
// 512 CTAs, 256 threads, pixel-pair mapping.
// ---------------------------------------------------------------------------
__global__ __launch_bounds__(256) void k_final(const float* __restrict__ x,
                                               float* __restrict__ out)
{
    __shared__ __align__(16) float cent2[9*2*CH_STR];
    __shared__ float csq_s[9];

    int bid = blockIdx.x;
    int b   = bid >> 8;
    int blk = bid & 255;
    int sy  = blk >> 4, sx = blk & 15;
    int tid = threadIdx.x;

    stage_cent(g_cent1, cent2, csq_s, b, sy, sx, tid);

    int pp  = tid >> 1;
    int h   = tid & 1;
    int row = pp >> 3;
    int col2= (pp & 7)*2;
    int n0  = (sy*SS + row)*WW + sx*SS + col2;
    const float* xp = x + (size_t)b*CC*NPIX + (size_t)(h*32)*NPIX + n0;

    float acc[2][9];
    dot9p(xp, (const float4*)cent2, h, acc);

    int n = n0 + h;                     // this thread's pixel index
    float e[9];
    softmax9(acc[h], csq_s, sy, sx, e);

    float* obase = out + ((size_t)b*NSP << 16);
    #pragma unroll
    for (int k = 0; k < 9; k++) {
        int cy = sy + (k/3) - 1, cx = sx + (k%3) - 1;
        if (cy >= 0 && cy < NH && cx >= 0 && cx < NW)
            obase[((size_t)(cy*NW + cx) << 16) + n] = e[k];
    }
}

// ---------------------------------------------------------------------------
extern "C" void kernel_launch(void* const* d_in, const int* in_sizes, int n_in,
                              void* d_out, int out_size)
{
    const float* x = (const float*)d_in[0];
    float* out = (float*)d_out;

    k_means <<<BB*CC*16, 256>>>(x, out);
    k_iter0 <<<BB*NSP,   256>>>(x, out);
    k_update<<<BB*NSP,    64>>>();
    k_final <<<BB*NSP,   256>>>(x, out);
}

// round 9
// speedup vs baseline: 1.5796x; 1.0826x over previous
#include <cuda_runtime.h>

// Problem constants (fixed shapes: x = (2, 64, 256, 256) fp32, stoken_size = 16)
#define BB   2
#define CC   64
#define HH   256
#define WW   256
#define SS   16
#define NH   16
#define NW   16
#define NSP  256      // nH*nW
#define NPIX 65536    // H*W

// cent2 float layout: [k][half][36]; as float4: [k][18] (h*9 + 8 used + pad).
#define CH_STR 36

// Scratch (device globals; no allocations allowed)
__device__ float g_cent0[BB*NSP*CC];
__device__ float g_cent1[BB*NSP*CC];
// per-block partials: [b][blk][k(9)][c(64)]
__device__ float g_part [BB*NSP*9*64];
// per-block weight sums: [b][blk][k(9)]
__device__ float g_den0 [BB*NSP*9];

// ---------------------------------------------------------------------------
// K1: zero-fill (64 MB, evict-first) + per-block channel means.
// CTA = (b, c, block-row by). 2048 CTAs, 256 threads, fully coalesced LDG.128.
// ---------------------------------------------------------------------------
__global__ __launch_bounds__(256) void k_means(const float* __restrict__ x,
                                               float* __restrict__ out)
{
    int tid = threadIdx.x;
    int bid = blockIdx.x;

    // fire-and-forget STREAMING zero stores — out4[0 .. 4194304), no L2 pollution
    {
        float4 z = make_float4(0.f, 0.f, 0.f, 0.f);
        float4* oz = (float4*)out + (size_t)bid*2048;
        #pragma unroll
        for (int j = 0; j < 8; j++) __stcs(&oz[j*256 + tid], z);
    }

    int by  = bid & 15;
    int bc  = bid >> 4;          // b*64 + c
    int b   = bc >> 6, c = bc & 63;

    const float4* xp = (const float4*)(x + (size_t)bc*NPIX + (size_t)by*16*WW);
    int fc  = tid & 63;          // float4 column 0..63
    int g   = tid >> 6;          // row group 0..3

    float4 s = make_float4(0.f, 0.f, 0.f, 0.f);
    #pragma unroll
    for (int r = 0; r < 4; r++) {
        float4 v = xp[(g*4 + r)*64 + fc];
        s.x += v.x; s.y += v.y; s.z += v.z; s.w += v.w;
    }

    __shared__ float4 sm4[4][64];
    __shared__ float  smc[64];
    sm4[g][fc] = s;
    __syncthreads();

    if (tid < 64) {
        float4 a = sm4[0][tid], b4 = sm4[1][tid], c4 = sm4[2][tid], d4 = sm4[3][tid];
        smc[tid] = (a.x+a.y+a.z+a.w) + (b4.x+b4.y+b4.z+b4.w)
                 + (c4.x+c4.y+c4.z+c4.w) + (d4.x+d4.y+d4.z+d4.w);
    }
    __syncthreads();

    if (tid < 16) {
        float m = (smc[4*tid] + smc[4*tid+1] + smc[4*tid+2] + smc[4*tid+3]) * (1.f/256.f);
        g_cent0[((size_t)(b*NSP + by*16 + tid))*CC + c] = m;
    }
}

// ---------------------------------------------------------------------------
// Shared helper: stage 9 candidate centroids into cent2[k][h][CH_STR] + csq.
// ---------------------------------------------------------------------------
__device__ __forceinline__ void stage_cent(const float* __restrict__ cent,
                                           float* cent2, float* csq_s,
                                           int b, int sy, int sx, int tid)
{
    for (int i = tid; i < 9*64; i += 256) {
        int k = i >> 6, c = i & 63;
        int cy = sy + (k/3) - 1, cx = sx + (k%3) - 1;
        float v = 0.f;
        if (cy >= 0 && cy < NH && cx >= 0 && cx < NW)
            v = cent[((size_t)(b*NSP + cy*NW + cx))*CC + c];
        cent2[k*(2*CH_STR) + (c >> 5)*CH_STR + (c & 31)] = v;
    }
    __syncthreads();
    if (tid < 18) {
        int k = tid >> 1, h = tid & 1;
        float s = 0.f;
        #pragma unroll 8
        for (int c = 0; c < 32; c++) {
            float v = cent2[k*(2*CH_STR) + h*CH_STR + c];
            s = fmaf(v, v, s);
        }
        if (h == 0) csq_s[k] = s;
        __syncwarp(0x0003ffffu);
        if (h == 1) csq_s[k] += s;
    }
    __syncthreads();
}

// ---------------------------------------------------------------------------
// Shared helper: pixel-pair dots. Thread covers 2 pixels (float2 loads) x 32
// channels (half h). Then merge halves via shfl.
// ---------------------------------------------------------------------------
__device__ __forceinline__ void dot9p(const float* xp, const float4* cent4,
                                      int h, float acc[2][9])
{
    #pragma unroll
    for (int k = 0; k < 9; k++) { acc[0][k] = 0.f; acc[1][k] = 0.f; }

    #pragma unroll
    for (int c8 = 0; c8 < 4; c8++) {
        float2 p[8];
        #pragma unroll
        for (int i = 0; i < 8; i++)
            p[i] = *(const float2*)(xp + (size_t)(c8*8 + i)*NPIX);
        #pragma unroll
        for (int g = 0; g < 2; g++) {
            #pragma unroll
            for (int k = 0; k < 9; k++) {
                float4 cv = cent4[k*18 + h*9 + c8*2 + g];
                acc[0][k] = fmaf(p[g*4+0].x, cv.x, acc[0][k]);
                acc[1][k] = fmaf(p[g*4+0].y, cv.x, acc[1][k]);
                acc[0][k] = fmaf(p[g*4+1].x, cv.y, acc[0][k]);
                acc[1][k] = fmaf(p[g*4+1].y, cv.y, acc[1][k]);
                acc[0][k] = fmaf(p[g*4+2].x, cv.z, acc[0][k]);
                acc[1][k] = fmaf(p[g*4+2].y, cv.z, acc[1][k]);
                acc[0][k] = fmaf(p[g*4+3].x, cv.w, acc[0][k]);
                acc[1][k] = fmaf(p[g*4+3].y, cv.w, acc[1][k]);
            }
        }
    }
    #pragma unroll
    for (int k = 0; k < 9; k++) {
        acc[0][k] += __shfl_xor_sync(0xffffffffu, acc[0][k], 1);
        acc[1][k] += __shfl_xor_sync(0xffffffffu, acc[1][k], 1);
    }
}

// ---------------------------------------------------------------------------
// Shared helper: softmax for this thread's pixel.
// ---------------------------------------------------------------------------
__device__ __forceinline__ void softmax9(const float* dot, const float* csq_s,
                                         int sy, int sx, float* e)
{
    float l[9];
    float m = -1e30f;
    #pragma unroll
    for (int k = 0; k < 9; k++) {
        int cy = sy + (k/3) - 1, cx = sx + (k%3) - 1;
        bool valid = (cy >= 0 && cy < NH && cx >= 0 && cx < NW);
        l[k] = valid ? (2.f*dot[k] - csq_s[k]) : -1e30f;
        m = fmaxf(m, l[k]);
    }
    float ssum = 0.f;
    #pragma unroll
    for (int k = 0; k < 9; k++) {
        e[k] = (l[k] > -1e29f) ? __expf(l[k] - m) : 0.f;
        ssum += e[k];
    }
    float inv = 1.f / ssum;
    #pragma unroll
    for (int k = 0; k < 9; k++) e[k] *= inv;
}

// ---------------------------------------------------------------------------
// K2: zero-fill (48 MB, evict-first) + iteration 0 over FULL blocks.
// 512 CTAs, 256 threads: thread = (pp 0..127, h 0..1).
// ---------------------------------------------------------------------------
__global__ __launch_bounds__(256) void k_iter0(const float* __restrict__ x,
                                               float* __restrict__ out)
{
    __shared__ __align__(16) float cent2[9*2*CH_STR];
    __shared__ float csq_s[9];
    __shared__ float Wsh[256*9];
    __shared__ float dsm[8][9];

    int tid = threadIdx.x;
    int bid = blockIdx.x;

    // streaming zero stores — out4[4194304 .. 7340032)
    {
        float4 z = make_float4(0.f, 0.f, 0.f, 0.f);
        float4* oz = (float4*)out + 4194304 + (size_t)bid*6144;
        #pragma unroll
        for (int j = 0; j < 24; j++) __stcs(&oz[j*256 + tid], z);
    }

    int b   = bid >> 8;
    int blk = bid & 255;
    int sy  = blk >> 4, sx = blk & 15;

    stage_cent(g_cent0, cent2, csq_s, b, sy, sx, tid);

    // phase B
    int pp  = tid >> 1;                 // pixel pair 0..127
    int h   = tid & 1;                  // channel half
    int row = pp >> 3;
    int col2= (pp & 7)*2;
    int n0  = (sy*SS + row)*WW + sx*SS + col2;
    const float* xp = x + (size_t)b*CC*NPIX + (size_t)(h*32)*NPIX + n0;

    float acc[2][9];
    dot9p(xp, (const float4*)cent2, h, acc);

    int pix = pp*2 + h;                 // this thread's pixel
    float e[9];
    softmax9(acc[h], csq_s, sy, sx, e);

    #pragma unroll
    for (int k = 0; k < 9; k++) Wsh[pix*9 + k] = e[k];

    // den[k] over all 256 pixels (each lane owns a distinct pixel)
    {
        int wid = tid >> 5, lane = tid & 31;
        #pragma unroll
        for (int k = 0; k < 9; k++) {
            float v = e[k];
            #pragma unroll
            for (int o = 16; o > 0; o >>= 1) v += __shfl_xor_sync(0xffffffffu, v, o);
            if (lane == 0) dsm[wid][k] = v;
        }
        __syncthreads();
        if (tid < 9) {
            float s = 0.f;
            #pragma unroll
            for (int w = 0; w < 8; w++) s += dsm[w][tid];
            g_den0[((size_t)(b*NSP + blk))*9 + tid] = s;
        }
    }

    // phase C: warp wid -> channels [wid*8, wid*8+8) in 2 groups of 4.
    int wid = tid >> 5, lane = tid & 31;
    const float* xt = x + (size_t)b*CC*NPIX + (size_t)(sy*SS)*WW + sx*SS;
    float* pdst = g_part + ((size_t)(b*NSP + blk)*9)*64;

    #pragma unroll
    for (int grp = 0; grp < 2; grp++) {
        int cbase = wid*8 + grp*4;
        float pacc[4][9];
        #pragma unroll
        for (int cc = 0; cc < 4; cc++)
            #pragma unroll
            for (int k = 0; k < 9; k++) pacc[cc][k] = 0.f;

        #pragma unroll
        for (int j = 0; j < 8; j++) {
            int px = j*32 + lane;
            int prow = px >> 4, pcol = px & 15;
            float w[9];
            #pragma unroll
            for (int k = 0; k < 9; k++) w[k] = Wsh[px*9 + k];
            #pragma unroll
            for (int cc = 0; cc < 4; cc++) {
                float pv = xt[(size_t)(cbase + cc)*NPIX + prow*WW + pcol];
                #pragma unroll
                for (int k = 0; k < 9; k++) pacc[cc][k] = fmaf(w[k], pv, pacc[cc][k]);
            }
        }
        #pragma unroll
        for (int cc = 0; cc < 4; cc++)
            #pragma unroll
            for (int k = 0; k < 9; k++)
                #pragma unroll
                for (int o = 16; o > 0; o >>= 1)
                    pacc[cc][k] += __shfl_xor_sync(0xffffffffu, pacc[cc][k], o);
        #pragma unroll
        for (int k = 0; k < 9; k++) {
            if (lane == k) {
                #pragma unroll
                for (int cc = 0; cc < 4; cc++)
                    pdst[(size_t)k*64 + cbase + cc] = pacc[cc][k];
            }
        }
    }
}

// ---------------------------------------------------------------------------
// K3: zero-fill (16 MB, evict-first) + gather centroid update (no atomics).
// grid = 512 (b,s), block = 256 (tid<64 compute; all threads zero).
// ---------------------------------------------------------------------------
__global__ __launch_bounds__(256) void k_update(float* __restrict__ out)
{
    int tid = threadIdx.x;
    int bid = blockIdx.x;

    // streaming zero stores — out4[7340032 .. 8388608)
    {
        float4 z = make_float4(0.f, 0.f, 0.f, 0.f);
        float4* oz = (float4*)out + 7340032 + (size_t)bid*2048;
        #pragma unroll
        for (int j = 0; j < 8; j++) __stcs(&oz[j*256 + tid], z);
    }

    int b   = bid >> 8;
    int s   = bid & 255;
    int sy  = s >> 4, sx = s & 15;

    __shared__ float dsm[9];
    if (tid < 9) {
        int dy = tid/3 - 1, dx = tid%3 - 1;
        int ny = sy + dy, nx = sx + dx;
        float d = 0.f;
        if (ny >= 0 && ny < NH && nx >= 0 && nx < NW)
            d = g_den0[((size_t)(b*NSP + ny*NW + nx))*9 + (8 - tid)];
        dsm[tid] = d;
    }
    __syncthreads();

    if (tid < 64) {
        int c = tid;
        float den = 0.f;
        #pragma unroll
        for (int j = 0; j < 9; j++) den += dsm[j];

        float num = 0.f;
        #pragma unroll
        for (int j = 0; j < 9; j++) {
            int dy = j/3 - 1, dx = j%3 - 1;
            int ny = sy + dy, nx = sx + dx;
            if (ny >= 0 && ny < NH && nx >= 0 && nx < NW)
                num += g_part[((size_t)((b*NSP + ny*NW + nx)*9 + (8 - j)))*64 + c];
        }
        g_cent1[((size_t)(b*NSP + s))*CC + c] = num / (den + 1e-16f);
    }
}

// ---------------------------------------------------------------------------
// K4: final weights over FULL blocks, scattered (evict-first) into the
// pre-zeroed output. 512 CTAs, 256 threads, pixel-pair mapping.
// ---------------------------------------------------------------------------
__global__ __launch_bounds__(256) void k_final(const float* __restrict__ x,
                                               float* __restrict__ out)
{
    __shared__ __align__(16) float cent2[9*2*CH_STR];
    __shared__ float csq_s[9];

    int bid = blockIdx.x;
    int b   = bid >> 8;
    int blk = bid & 255;
    int sy  = blk >> 4, sx = blk & 15;
    int tid = threadIdx.x;

    stage_cent(g_cent1, cent2, csq_s, b, sy, sx, tid);

    int pp  = tid >> 1;
    int h   = tid & 1;
    int row = pp >> 3;
    int col2= (pp & 7)*2;
    int n0  = (sy*SS + row)*WW + sx*SS + col2;
    const float* xp = x + (size_t)b*CC*NPIX + (size_t)(h*32)*NPIX + n0;

    float acc[2][9];
    dot9p(xp, (const float4*)cent2, h, acc);

    int n = n0 + h;                     // this thread's pixel index
    float e[9];
    softmax9(acc[h], csq_s, sy, sx, e);

    float* obase = out + ((size_t)b*NSP << 16);
    #pragma unroll
    for (int k = 0; k < 9; k++) {
        int cy = sy + (k/3) - 1, cx = sx + (k%3) - 1;
        if (cy >= 0 && cy < NH && cx >= 0 && cx < NW)
            __stcs(&obase[((size_t)(cy*NW + cx) << 16) + n], e[k]);
    }
}

// ---------------------------------------------------------------------------
extern "C" void kernel_launch(void* const* d_in, const int* in_sizes, int n_in,
                              void* d_out, int out_size)
{
    const float* x = (const float*)d_in[0];
    float* out = (float*)d_out;

    k_means <<<BB*CC*16, 256>>>(x, out);
    k_iter0 <<<BB*NSP,   256>>>(x, out);
    k_update<<<BB*NSP,   256>>>(out);
    k_final <<<BB*NSP,   256>>>(x, out);
}